// round 2
// baseline (speedup 1.0000x reference)
#include <cuda_runtime.h>
#include <math_constants.h>

#define NB 1024

// Globals built by prep each launch (deterministic).
__device__ float4 g_tabm[NB];   // {m1, m2, m3, pad} per bucket (INF if unused)
__device__ float4 g_tabv[NB];   // {v0, v1, v2, v3} candidate code values
__device__ float  g_sorted[128];
__device__ float  g_mid[127];
__device__ float  g_scale, g_offs;
__device__ int    g_bad;

// Shared bucket function — MUST be identical ops in prep and main.
__device__ __forceinline__ int bucket_of(float v, float scale, float offs) {
    int b = (int)__fmaf_rn(v, scale, offs);   // FFMA + F2I.TRUNC (monotone)
    b = max(0, min(NB - 1, b));
    return b;
}

// ---------------------------------------------------------------------------
// Prep: sort codebook, build midpoints, build uniform-grid bucket tables.
// One block, 1024 threads. Trivial cost.
// ---------------------------------------------------------------------------
__global__ void vq_prep(const float* __restrict__ w) {
    __shared__ float sw[128];
    __shared__ float ss[128];
    __shared__ float smd[127];
    __shared__ int   sfb[127];
    __shared__ float s_scale, s_offs;

    const int tid = threadIdx.x;

    if (tid < 128) sw[tid] = w[tid];
    if (tid == 0) g_bad = 0;
    __syncthreads();

    if (tid < 128) {
        float v = sw[tid];
        int rank = 0;
#pragma unroll
        for (int k = 0; k < 128; ++k) {
            float u = sw[k];
            rank += ((u < v) || (u == v && k < tid)) ? 1 : 0;
        }
        ss[rank] = v;   // unique ranks
    }
    __syncthreads();

    if (tid < 128) g_sorted[tid] = ss[tid];
    if (tid < 127) {
        float m = 0.5f * (ss[tid] + ss[tid + 1]);
        smd[tid] = m;
        g_mid[tid] = m;
    }
    __syncthreads();

    if (tid == 0) {
        float lo = smd[0], hi = smd[126];
        float d = hi - lo;
        float scale, offs;
        if (d > 0.0f && isfinite(d)) {
            scale = (float)NB / d;
            offs  = -lo * scale;
            if (!isfinite(scale) || !isfinite(offs)) { scale = 0.0f; offs = 0.0f; }
        } else { scale = 0.0f; offs = 0.0f; }   // degenerate -> all bucket 0 -> bad flag -> slow path
        s_scale = scale; s_offs = offs;
        g_scale = scale; g_offs = offs;
    }
    __syncthreads();

    const float scale = s_scale, offs = s_offs;
    if (tid < 127) sfb[tid] = bucket_of(smd[tid], scale, offs);  // non-decreasing
    __syncthreads();

    // One thread per bucket: binary lower_bound over sfb for b and b+1.
    {
        const int b = tid;  // 0..1023
        int lo = 0, hi = 127;
        while (lo < hi) { int m = (lo + hi) >> 1; if (sfb[m] < b) lo = m + 1; else hi = m; }
        const int base = lo;
        lo = base; hi = 127;
        while (lo < hi) { int m = (lo + hi) >> 1; if (sfb[m] < b + 1) lo = m + 1; else hi = m; }
        const int cnt = lo - base;  // midpoints inside bucket b

        const float INF = CUDART_INF_F;
        float4 tm, tv;
        tm.x = (cnt > 0) ? smd[base]     : INF;
        tm.y = (cnt > 1) ? smd[base + 1] : INF;
        tm.z = (cnt > 2) ? smd[base + 2] : INF;
        tm.w = INF;
        // candidate codes: indices base .. base+min(cnt,3)
        tv.x = ss[base];
        tv.y = ss[base + min(1, cnt)];
        tv.z = ss[base + min(2, cnt)];
        tv.w = ss[base + min(3, cnt)];
        g_tabm[b] = tm;
        g_tabv[b] = tv;
        if (cnt > 3) atomicOr(&g_bad, 1);
    }
}

// ---------------------------------------------------------------------------
// Main kernel: 1 FFMA-bucket + 2 conflict-friendly LDS.128 + 3 compare/select
// per element. Grid-stride over float4.
// ---------------------------------------------------------------------------
#define VQ_THREADS 256

__global__ __launch_bounds__(VQ_THREADS, 7)
void vq_kernel(const float4* __restrict__ x4, float4* __restrict__ o4, int n4,
               const float* __restrict__ xt, float* __restrict__ ot, int n_tail) {
    __shared__ float4 sm_m[NB];
    __shared__ float4 sm_v[NB];

    const int tid = threadIdx.x;
    // Fill tables (coalesced float4 copies).
#pragma unroll
    for (int i = tid; i < NB; i += VQ_THREADS) {
        sm_m[i] = g_tabm[i];
        sm_v[i] = g_tabv[i];
    }
    const float scale = g_scale;
    const float offs  = g_offs;
    const int   bad   = g_bad;
    __syncthreads();

    const int idx0   = blockIdx.x * VQ_THREADS + tid;
    const int stride = gridDim.x * VQ_THREADS;

    if (!bad) {
        for (int i = idx0; i < n4; i += stride) {
            float4 in = x4[i];
            float xs[4] = {in.x, in.y, in.z, in.w};
            float rr[4];
#pragma unroll
            for (int e = 0; e < 4; ++e) {
                const float xv = xs[e];
                const int b = bucket_of(xv, scale, offs);
                const float4 m = sm_m[b];
                const float4 v = sm_v[b];
                float r = v.x;
                r = (xv > m.x) ? v.y : r;
                r = (xv > m.y) ? v.z : r;
                r = (xv > m.z) ? v.w : r;
                rr[e] = r;
            }
            float4 ov; ov.x = rr[0]; ov.y = rr[1]; ov.z = rr[2]; ov.w = rr[3];
            o4[i] = ov;
        }
    } else {
        // Rare fallback: full binary search over midpoints (correctness path).
        for (int i = idx0; i < n4; i += stride) {
            float4 in = x4[i];
            float xs[4] = {in.x, in.y, in.z, in.w};
            float rr[4];
#pragma unroll
            for (int e = 0; e < 4; ++e) {
                const float xv = xs[e];
                int base = 0;
#pragma unroll
                for (int half = 64; half >= 1; half >>= 1) {
                    float m = __ldg(g_mid + base + half - 1);
                    if (m < xv) base += half;
                }
                rr[e] = __ldg(g_sorted + base);
            }
            float4 ov; ov.x = rr[0]; ov.y = rr[1]; ov.z = rr[2]; ov.w = rr[3];
            o4[i] = ov;
        }
    }

    // Tail (n % 4), negligible; always via exact binary search.
    if (blockIdx.x == 0 && tid == 0) {
        for (int t = 0; t < n_tail; ++t) {
            const float xv = xt[t];
            int base = 0;
#pragma unroll
            for (int half = 64; half >= 1; half >>= 1) {
                float m = __ldg(g_mid + base + half - 1);
                if (m < xv) base += half;
            }
            ot[t] = __ldg(g_sorted + base);
        }
    }
}

extern "C" void kernel_launch(void* const* d_in, const int* in_sizes, int n_in,
                              void* d_out, int out_size) {
    const float* x = (const float*)d_in[0];   // [16,1,512,512] fp32
    const float* w = (const float*)d_in[1];   // [128,1] fp32
    float* out = (float*)d_out;

    const int n = in_sizes[0];
    const int n4 = n >> 2;
    const int n_tail = n & 3;

    vq_prep<<<1, 1024>>>(w);

    const int grid = 148 * 7;   // 7 blocks/SM (smem-limited), one full wave
    vq_kernel<<<grid, VQ_THREADS>>>((const float4*)x, (float4*)out, n4,
                                    x + (size_t)n4 * 4, out + (size_t)n4 * 4, n_tail);
}

// round 3
// speedup vs baseline: 1.3617x; 1.3617x over previous
#include <cuda_runtime.h>
#include <math_constants.h>

#define NB 4096
#define VQ_THREADS 256
#define VQ_BLOCKS_PER_SM 6

// Globals built by prep each launch (deterministic).
__device__ float         g_sorted[128];
__device__ float         g_mid[128];        // 127 used, [127] = +INF pad
__device__ unsigned char g_base[NB];        // lower_bound of midpoints at bucket start; 255 = slow path
__device__ float         g_scale, g_offs;

// Shared bucket function — identical ops in prep and main (monotone non-decreasing).
__device__ __forceinline__ int bucket_of(float v, float scale, float offs) {
    int b = (int)__fmaf_rn(v, scale, offs);   // FFMA + F2I.TRUNC
    return max(0, min(NB - 1, b));
}

// ---------------------------------------------------------------------------
// Prep: sort 128 codes by rank, build 127 midpoints, build u8 bucket->base LUT.
// One block of 1024 threads; trivial cost.
// ---------------------------------------------------------------------------
__global__ void vq_prep(const float* __restrict__ w) {
    __shared__ float sw[128];
    __shared__ float ss[128];
    __shared__ float smd[127];
    __shared__ int   sfb[127];
    __shared__ float s_scale, s_offs;

    const int tid = threadIdx.x;

    if (tid < 128) sw[tid] = w[tid];
    __syncthreads();

    if (tid < 128) {
        float v = sw[tid];
        int rank = 0;
#pragma unroll
        for (int k = 0; k < 128; ++k) {
            float u = sw[k];
            rank += ((u < v) || (u == v && k < tid)) ? 1 : 0;
        }
        ss[rank] = v;   // unique ranks
    }
    __syncthreads();

    if (tid < 128) g_sorted[tid] = ss[tid];
    if (tid < 127) {
        float m = 0.5f * (ss[tid] + ss[tid + 1]);
        smd[tid] = m;
        g_mid[tid] = m;
    }
    if (tid == 127) g_mid[127] = CUDART_INF_F;
    __syncthreads();

    if (tid == 0) {
        float lo = smd[0], hi = smd[126];
        float d = hi - lo;
        float scale, offs;
        if (d > 0.0f && isfinite(d)) {
            scale = (float)NB / d;
            offs  = -lo * scale;
            if (!isfinite(scale) || !isfinite(offs)) { scale = 0.0f; offs = 0.0f; }
        } else { scale = 0.0f; offs = 0.0f; }   // degenerate -> everything slow path
        s_scale = scale; s_offs = offs;
        g_scale = scale; g_offs = offs;
    }
    __syncthreads();

    const float scale = s_scale, offs = s_offs;
    if (tid < 127) sfb[tid] = bucket_of(smd[tid], scale, offs);  // non-decreasing
    __syncthreads();

    // Each thread builds 4 consecutive buckets, packs them into one uchar4.
    const int b0 = tid * 4;
    uchar4 pk;
    unsigned char* pp = (unsigned char*)&pk;
#pragma unroll
    for (int q = 0; q < 4; ++q) {
        const int b = b0 + q;
        int lo = 0, hi = 127;
        while (lo < hi) { int m = (lo + hi) >> 1; if (sfb[m] < b) lo = m + 1; else hi = m; }
        const int base = lo;
        lo = base; hi = 127;
        while (lo < hi) { int m = (lo + hi) >> 1; if (sfb[m] < b + 1) lo = m + 1; else hi = m; }
        const int cnt = lo - base;                 // midpoints inside bucket b
        pp[q] = (cnt > 2) ? 255 : (unsigned char)base;
    }
    ((uchar4*)g_base)[tid] = pk;
}

// ---------------------------------------------------------------------------
// Main: per element -> bucket (FFMA+F2I), u8 base LUT, two conflict-free
// replicated-mid compares, conflict-free replicated-code gather.
// ---------------------------------------------------------------------------
__global__ __launch_bounds__(VQ_THREADS, VQ_BLOCKS_PER_SM)
void vq_kernel(const float4* __restrict__ x4, float4* __restrict__ o4, int n4,
               const float* __restrict__ xt, float* __restrict__ ot, int n_tail) {
    __shared__ unsigned char sbase[NB];         // 4 KB
    __shared__ float smid[128][32];             // 16 KB, replicated: bank == lane
    __shared__ float scode[128][32];            // 16 KB, replicated: bank == lane

    const int tid  = threadIdx.x;
    const int lane = tid & 31;

    // Fill LUTs (coalesced).
    ((uint4*)sbase)[tid] = ((const uint4*)g_base)[tid];   // 256 * 16B = 4096B
#pragma unroll
    for (int i = tid; i < 128 * 32; i += VQ_THREADS) {
        const int row = i >> 5, col = i & 31;
        smid[row][col]  = g_mid[row];
        scode[row][col] = g_sorted[row];
    }
    const float scale = g_scale;
    const float offs  = g_offs;
    __syncthreads();

    const int idx0   = blockIdx.x * VQ_THREADS + tid;
    const int stride = gridDim.x * VQ_THREADS;

    for (int i = idx0; i < n4; i += stride) {
        float4 in = x4[i];
        float xs[4] = {in.x, in.y, in.z, in.w};
        float rr[4];
#pragma unroll
        for (int e = 0; e < 4; ++e) {
            const float xv = xs[e];
            const int b = bucket_of(xv, scale, offs);
            const int base = (int)sbase[b];
            int j;
            if (base != 255) {
                const float m0 = smid[min(base,     126)][lane];
                const float m1 = smid[min(base + 1, 126)][lane];
                j = base + ((m0 < xv) ? 1 : 0) + ((m1 < xv) ? 1 : 0);
                j = min(j, 127);
            } else {
                // Rare: >2 midpoints in bucket -> exact lower_bound on
                // conflict-free replicated table.
                j = 0;
#pragma unroll
                for (int half = 64; half >= 1; half >>= 1) {
                    const int t = j + half - 1;
                    if (t < 127 && smid[t][lane] < xv) j += half;
                }
            }
            rr[e] = scode[j][lane];   // conflict-free gather
        }
        float4 ov; ov.x = rr[0]; ov.y = rr[1]; ov.z = rr[2]; ov.w = rr[3];
        o4[i] = ov;
    }

    // Tail (n % 4), negligible; exact search on replicated tables.
    if (blockIdx.x == 0 && tid == 0) {
        for (int t = 0; t < n_tail; ++t) {
            const float xv = xt[t];
            int j = 0;
#pragma unroll
            for (int half = 64; half >= 1; half >>= 1) {
                const int u = j + half - 1;
                if (u < 127 && smid[u][0] < xv) j += half;
            }
            ot[t] = scode[j][0];
        }
    }
}

extern "C" void kernel_launch(void* const* d_in, const int* in_sizes, int n_in,
                              void* d_out, int out_size) {
    const float* x = (const float*)d_in[0];   // [16,1,512,512] fp32
    const float* w = (const float*)d_in[1];   // [128,1] fp32
    float* out = (float*)d_out;

    const int n = in_sizes[0];
    const int n4 = n >> 2;
    const int n_tail = n & 3;

    vq_prep<<<1, 1024>>>(w);

    const int grid = 148 * VQ_BLOCKS_PER_SM;   // one full resident wave, grid-stride
    vq_kernel<<<grid, VQ_THREADS>>>((const float4*)x, (float4*)out, n4,
                                    x + (size_t)n4 * 4, out + (size_t)n4 * 4, n_tail);
}

// round 4
// speedup vs baseline: 1.3643x; 1.0019x over previous
#include <cuda_runtime.h>
#include <math_constants.h>

#define NB 4096
#define VQ_THREADS 256
#define ILP 4            // float4s per thread per iteration (16 elements)

// Globals built by prep each launch (deterministic).
__device__ float         g_sorted[129];     // [128] pad = 0
__device__ float         g_mid[130];        // 127 used, [127..129] = +INF pad
__device__ unsigned char g_base[NB];        // midpoint lower_bound at bucket start; 128 = slow-path sentinel
__device__ float         g_scale, g_offs;

// Shared bucket function — identical ops in prep and main (monotone non-decreasing).
__device__ __forceinline__ int bucket_of(float v, float scale, float offs) {
    int b = (int)__fmaf_rn(v, scale, offs);   // FFMA + F2I.TRUNC
    return max(0, min(NB - 1, b));
}

// ---------------------------------------------------------------------------
// Prep: sort 128 codes by rank, build 127 midpoints, build u8 bucket->base LUT.
// One block of 1024 threads; trivial cost.
// ---------------------------------------------------------------------------
__global__ void vq_prep(const float* __restrict__ w) {
    __shared__ float sw[128];
    __shared__ float ss[128];
    __shared__ float smd[127];
    __shared__ int   sfb[127];
    __shared__ float s_scale, s_offs;

    const int tid = threadIdx.x;

    if (tid < 128) sw[tid] = w[tid];
    __syncthreads();

    if (tid < 128) {
        float v = sw[tid];
        int rank = 0;
#pragma unroll
        for (int k = 0; k < 128; ++k) {
            float u = sw[k];
            rank += ((u < v) || (u == v && k < tid)) ? 1 : 0;
        }
        ss[rank] = v;   // unique ranks
    }
    __syncthreads();

    if (tid < 128) g_sorted[tid] = ss[tid];
    if (tid == 128) g_sorted[128] = 0.0f;                 // pad (sentinel j==128 reads this, discarded)
    if (tid < 127) {
        float m = 0.5f * (ss[tid] + ss[tid + 1]);
        smd[tid] = m;
        g_mid[tid] = m;
    }
    if (tid >= 127 && tid < 130) g_mid[tid] = CUDART_INF_F;  // INF pad rows
    __syncthreads();

    if (tid == 0) {
        float lo = smd[0], hi = smd[126];
        float d = hi - lo;
        float scale, offs;
        if (d > 0.0f && isfinite(d)) {
            scale = (float)NB / d;
            offs  = -lo * scale;
            if (!isfinite(scale) || !isfinite(offs)) { scale = 0.0f; offs = 0.0f; }
        } else { scale = 0.0f; offs = 0.0f; }
        s_scale = scale; s_offs = offs;
        g_scale = scale; g_offs = offs;
    }
    __syncthreads();

    const float scale = s_scale, offs = s_offs;
    if (tid < 127) sfb[tid] = bucket_of(smd[tid], scale, offs);  // non-decreasing
    __syncthreads();

    // Each thread builds 4 consecutive buckets, packs into one uchar4.
    const int b0 = tid * 4;
    uchar4 pk;
    unsigned char* pp = (unsigned char*)&pk;
#pragma unroll
    for (int q = 0; q < 4; ++q) {
        const int b = b0 + q;
        int lo = 0, hi = 127;
        while (lo < hi) { int m = (lo + hi) >> 1; if (sfb[m] < b) lo = m + 1; else hi = m; }
        const int base = lo;
        lo = base; hi = 127;
        while (lo < hi) { int m = (lo + hi) >> 1; if (sfb[m] < b + 1) lo = m + 1; else hi = m; }
        const int cnt = lo - base;                 // midpoints inside bucket b
        pp[q] = (cnt > 2) ? (unsigned char)128 : (unsigned char)base;  // sentinel lands on INF pad
    }
    ((uchar4*)g_base)[tid] = pk;
}

// ---------------------------------------------------------------------------
// Main: per element -> bucket (FFMA+F2I+clamp), u8 base LUT, two compares vs
// INF-padded conflict-free replicated midpoints, conflict-free code gather.
// 16 elements per thread per iteration for latency hiding.
// ---------------------------------------------------------------------------
__global__ __launch_bounds__(VQ_THREADS, 4)
void vq_kernel(const float4* __restrict__ x4, float4* __restrict__ o4, int n4,
               const float* __restrict__ xt, float* __restrict__ ot, int n_tail) {
    __shared__ unsigned char sbase[NB];         // 4 KB
    __shared__ float smid[130][32];             // replicated, bank == lane; rows 127..129 = +INF
    __shared__ float scode[129][32];            // replicated, bank == lane; row 128 = pad

    const int tid  = threadIdx.x;
    const int lane = tid & 31;

    // Fill LUTs (coalesced).
    ((uint4*)sbase)[tid] = ((const uint4*)g_base)[tid];   // 256 * 16B = 4096B
#pragma unroll
    for (int i = tid; i < 130 * 32; i += VQ_THREADS) {
        const int row = i >> 5, col = i & 31;
        smid[row][col] = g_mid[row];
        if (row < 129) scode[row][col] = g_sorted[row];
    }
    const float scale = g_scale;
    const float offs  = g_offs;
    __syncthreads();

    const int chunk = VQ_THREADS * ILP;

    for (int c0 = blockIdx.x * chunk; c0 < n4; c0 += gridDim.x * chunk) {
        float4 v[ILP];
        int have[ILP];
#pragma unroll
        for (int k = 0; k < ILP; ++k) {
            const int idx = c0 + k * VQ_THREADS + tid;
            have[k] = (idx < n4);
            if (have[k]) v[k] = x4[idx];
        }

        int bad = 0;
        float4 o[ILP];
#pragma unroll
        for (int k = 0; k < ILP; ++k) {
            float xs[4] = {v[k].x, v[k].y, v[k].z, v[k].w};
            float rr[4];
#pragma unroll
            for (int e = 0; e < 4; ++e) {
                const float xv = xs[e];
                const int b = bucket_of(xv, scale, offs);
                const int base = (int)sbase[b];
                bad |= base >> 7;                       // base==128 -> sentinel
                const float m0 = smid[base][lane];
                const float m1 = smid[base + 1][lane];  // safe: INF pad rows
                const int j = base + ((m0 < xv) ? 1 : 0) + ((m1 < xv) ? 1 : 0);
                rr[e] = scode[j][lane];                 // conflict-free gather
            }
            o[k].x = rr[0]; o[k].y = rr[1]; o[k].z = rr[2]; o[k].w = rr[3];
        }

        if (bad) {
            // Essentially-never path: exact binary search on INF-padded table.
#pragma unroll
            for (int k = 0; k < ILP; ++k) {
                float xs[4] = {v[k].x, v[k].y, v[k].z, v[k].w};
                float rr[4];
#pragma unroll
                for (int e = 0; e < 4; ++e) {
                    const float xv = xs[e];
                    int j = 0;
#pragma unroll
                    for (int half = 64; half >= 1; half >>= 1)
                        if (smid[j + half - 1][lane] < xv) j += half;   // rows>=127 are INF
                    rr[e] = scode[j][lane];
                }
                o[k].x = rr[0]; o[k].y = rr[1]; o[k].z = rr[2]; o[k].w = rr[3];
            }
        }

#pragma unroll
        for (int k = 0; k < ILP; ++k) {
            const int idx = c0 + k * VQ_THREADS + tid;
            if (have[k]) o4[idx] = o[k];
        }
    }

    // Tail (n % 4), negligible; exact search.
    if (blockIdx.x == 0 && tid == 0) {
        for (int t = 0; t < n_tail; ++t) {
            const float xv = xt[t];
            int j = 0;
#pragma unroll
            for (int half = 64; half >= 1; half >>= 1)
                if (smid[j + half - 1][0] < xv) j += half;
            ot[t] = scode[j][0];
        }
    }
}

extern "C" void kernel_launch(void* const* d_in, const int* in_sizes, int n_in,
                              void* d_out, int out_size) {
    const float* x = (const float*)d_in[0];   // [16,1,512,512] fp32
    const float* w = (const float*)d_in[1];   // [128,1] fp32
    float* out = (float*)d_out;

    const int n = in_sizes[0];
    const int n4 = n >> 2;
    const int n_tail = n & 3;

    vq_prep<<<1, 1024>>>(w);

    const int chunk = VQ_THREADS * ILP;
    int grid = (n4 + chunk - 1) / chunk;      // exact cover: 1024 blocks for this shape
    if (grid < 1) grid = 1;
    vq_kernel<<<grid, VQ_THREADS>>>((const float4*)x, (float4*)out, n4,
                                    x + (size_t)n4 * 4, out + (size_t)n4 * 4, n_tail);
}

// round 5
// speedup vs baseline: 1.5496x; 1.1358x over previous
#include <cuda_runtime.h>
#include <math_constants.h>

#define NB 2048
#define VQ_THREADS 256
#define ILP 2            // float4s per thread per iteration (8 elements)

// Globals built by prep each launch (deterministic).
__device__ float2        g_tabA[NB];        // {vleft, mid} per bucket (mid=+INF if no midpoint)
__device__ float         g_tabB[NB];        // vright per bucket (NaN sentinel if >=2 midpoints)
__device__ float         g_sorted[129];     // sorted codes, [128] pad
__device__ float         g_mid[130];        // 127 midpoints, [127..129] = +INF
__device__ float         g_scale, g_offs;

// Shared bucket function — identical ops in prep and main (monotone non-decreasing).
__device__ __forceinline__ int bucket_of(float v, float scale, float offs) {
    int b = (int)__fmaf_rn(v, scale, offs);   // FFMA + F2I.TRUNC
    return max(0, min(NB - 1, b));
}

// ---------------------------------------------------------------------------
// Prep: sort 128 codes by rank, build 127 midpoints, build per-bucket
// {vleft, mid, vright} tables. One block of 1024 threads; trivial cost.
// ---------------------------------------------------------------------------
__global__ void vq_prep(const float* __restrict__ w) {
    __shared__ float sw[128];
    __shared__ float ss[128];
    __shared__ float smd[127];
    __shared__ int   sfb[127];
    __shared__ float s_scale, s_offs;

    const int tid = threadIdx.x;

    if (tid < 128) sw[tid] = w[tid];
    __syncthreads();

    if (tid < 128) {
        float v = sw[tid];
        int rank = 0;
#pragma unroll
        for (int k = 0; k < 128; ++k) {
            float u = sw[k];
            rank += ((u < v) || (u == v && k < tid)) ? 1 : 0;
        }
        ss[rank] = v;   // unique ranks
    }
    __syncthreads();

    if (tid < 128) g_sorted[tid] = ss[tid];
    if (tid == 128) g_sorted[128] = 0.0f;
    if (tid < 127) {
        float m = 0.5f * (ss[tid] + ss[tid + 1]);
        smd[tid] = m;
        g_mid[tid] = m;
    }
    if (tid >= 127 && tid < 130) g_mid[tid] = CUDART_INF_F;
    __syncthreads();

    if (tid == 0) {
        float lo = smd[0], hi = smd[126];
        float d = hi - lo;
        float scale, offs;
        if (d > 0.0f && isfinite(d)) {
            scale = (float)NB / d;
            offs  = -lo * scale;
            if (!isfinite(scale) || !isfinite(offs)) { scale = 0.0f; offs = 0.0f; }
        } else { scale = 0.0f; offs = 0.0f; }   // degenerate -> bucket0 has all mids -> NaN path
        s_scale = scale; s_offs = offs;
        g_scale = scale; g_offs = offs;
    }
    __syncthreads();

    const float scale = s_scale, offs = s_offs;
    if (tid < 127) sfb[tid] = bucket_of(smd[tid], scale, offs);  // non-decreasing
    __syncthreads();

    // Each thread builds NB/1024 consecutive buckets.
#pragma unroll
    for (int q = 0; q < NB / 1024; ++q) {
        const int b = tid * (NB / 1024) + q;
        int lo = 0, hi = 127;
        while (lo < hi) { int m = (lo + hi) >> 1; if (sfb[m] < b) lo = m + 1; else hi = m; }
        const int base = lo;                        // midpoints strictly before bucket b
        lo = base; hi = 127;
        while (lo < hi) { int m = (lo + hi) >> 1; if (sfb[m] < b + 1) lo = m + 1; else hi = m; }
        const int cnt = lo - base;                  // midpoints inside bucket b

        float2 A; float Bv;
        A.x = ss[base];                             // vleft (base <= 127 always)
        if (cnt == 0)      { A.y = CUDART_INF_F; Bv = A.x; }
        else if (cnt == 1) { A.y = smd[base];    Bv = ss[base + 1]; }
        else               { A.y = smd[base];    Bv = CUDART_NAN_F; }  // redo sentinel
        g_tabA[b] = A;
        g_tabB[b] = Bv;
    }
}

// Predicated shared load: r = (xv > mid) ? *addr : r, with a guaranteed @p LDS
// (no branch, inactive lanes touch no banks).
__device__ __forceinline__ void pred_lds_gt(float& r, float xv, float mid, unsigned addr) {
    asm volatile(
        "{ .reg .pred p; setp.gt.f32 p, %1, %2; @p ld.shared.f32 %0, [%3]; }"
        : "+f"(r) : "f"(xv), "f"(mid), "r"(addr));
}

// ---------------------------------------------------------------------------
// Main: per element -> bucket (FFMA+F2I+clamp) -> one LDS.64 {vl, mid} ->
// predicated LDS vr. NaN-sentinel redo path for >=2-midpoint buckets.
// ---------------------------------------------------------------------------
__global__ __launch_bounds__(VQ_THREADS, 6)
void vq_kernel(const float4* __restrict__ x4, float4* __restrict__ o4, int n4,
               const float* __restrict__ xt, float* __restrict__ ot, int n_tail) {
    __shared__ float2 tabA[NB];        // 16 KB
    __shared__ float  tabB[NB];        // 8 KB
    __shared__ float  smid2[130];      // compact, INF-padded (redo path only)
    __shared__ float  scode2[129];

    const int tid = threadIdx.x;

    // Fill tables (coalesced).
#pragma unroll
    for (int i = tid; i < NB; i += VQ_THREADS) {
        tabA[i] = g_tabA[i];
        tabB[i] = g_tabB[i];
    }
    if (tid < 130) smid2[tid] = g_mid[tid];
    if (tid < 129) scode2[tid] = g_sorted[tid];
    const float scale = g_scale;
    const float offs  = g_offs;
    __syncthreads();

    const unsigned tabB_base = (unsigned)__cvta_generic_to_shared(tabB);
    const int chunk = VQ_THREADS * ILP;

    for (int c0 = blockIdx.x * chunk; c0 < n4; c0 += gridDim.x * chunk) {
        float4 v[ILP];
        int have[ILP];
#pragma unroll
        for (int k = 0; k < ILP; ++k) {
            const int idx = c0 + k * VQ_THREADS + tid;
            have[k] = (idx < n4);
            if (have[k]) v[k] = x4[idx];
        }

        float4 o[ILP];
        int anynan = 0;
#pragma unroll
        for (int k = 0; k < ILP; ++k) {
            float xs[4] = {v[k].x, v[k].y, v[k].z, v[k].w};
            float rr[4];
#pragma unroll
            for (int e = 0; e < 4; ++e) {
                const float xv = xs[e];
                const int b = bucket_of(xv, scale, offs);
                const float2 a = tabA[b];          // {vleft, mid} — one LDS.64
                float r = a.x;
                pred_lds_gt(r, xv, a.y, tabB_base + (unsigned)b * 4u);
                anynan |= (r != r);                // NaN sentinel (or NaN input)
                rr[e] = r;
            }
            o[k].x = rr[0]; o[k].y = rr[1]; o[k].z = rr[2]; o[k].w = rr[3];
        }

        if (anynan) {
            // Rare: exact lower_bound on compact INF-padded tables.
#pragma unroll
            for (int k = 0; k < ILP; ++k) {
                float xs[4] = {v[k].x, v[k].y, v[k].z, v[k].w};
                float* ro = (float*)&o[k];
#pragma unroll
                for (int e = 0; e < 4; ++e) {
                    if (ro[e] != ro[e]) {
                        const float xv = xs[e];
                        int j = 0;
#pragma unroll
                        for (int half = 64; half >= 1; half >>= 1)
                            if (smid2[j + half - 1] < xv) j += half;
                        ro[e] = scode2[j];
                    }
                }
            }
        }

#pragma unroll
        for (int k = 0; k < ILP; ++k) {
            const int idx = c0 + k * VQ_THREADS + tid;
            if (have[k]) o4[idx] = o[k];
        }
    }

    // Tail (n % 4), negligible; exact search.
    if (blockIdx.x == 0 && tid == 0) {
        for (int t = 0; t < n_tail; ++t) {
            const float xv = xt[t];
            int j = 0;
#pragma unroll
            for (int half = 64; half >= 1; half >>= 1)
                if (smid2[j + half - 1] < xv) j += half;
            ot[t] = scode2[j];
        }
    }
}

extern "C" void kernel_launch(void* const* d_in, const int* in_sizes, int n_in,
                              void* d_out, int out_size) {
    const float* x = (const float*)d_in[0];   // [16,1,512,512] fp32
    const float* w = (const float*)d_in[1];   // [128,1] fp32
    float* out = (float*)d_out;

    const int n = in_sizes[0];
    const int n4 = n >> 2;
    const int n_tail = n & 3;

    vq_prep<<<1, 1024>>>(w);

    const int grid = 148 * 6;   // one resident wave (6 blocks/SM), grid-stride
    vq_kernel<<<grid, VQ_THREADS>>>((const float4*)x, (float4*)out, n4,
                                    x + (size_t)n4 * 4, out + (size_t)n4 * 4, n_tail);
}